// round 13
// baseline (speedup 1.0000x reference)
#include <cuda_runtime.h>
#include <cstdint>

// Problem shape (fixed by the dataset): B=512, S=1024, T=64
#define Bn 512
#define Sn 1024
#define Tn 64
#define WPB 4          // forward warps per block; each warp runs TWO chains
#define FWD_BLOCKS 64  // 64 blocks x 4 warps x 2 chains = 512
#define GOLD_BLOCKS 16 // gold on otherwise-idle SMs

typedef unsigned long long u64;

__device__ float g_z[Bn];
__device__ float g_sc[Bn];

__device__ __forceinline__ u64 ffma2(u64 a, u64 b, u64 c) {
    u64 d;
    asm("fma.rn.f32x2 %0, %1, %2, %3;" : "=l"(d) : "l"(a), "l"(b), "l"(c));
    return d;
}
__device__ __forceinline__ u64 fadd2(u64 a, u64 b) {
    u64 d;
    asm("add.rn.f32x2 %0, %1, %2;" : "=l"(d) : "l"(a), "l"(b));
    return d;
}
__device__ __forceinline__ u64 fmul2(u64 a, u64 b) {
    u64 d;
    asm("mul.rn.f32x2 %0, %1, %2;" : "=l"(d) : "l"(a), "l"(b));
    return d;
}
__device__ __forceinline__ u64 pk2(float a, float b) {
    u64 d;
    asm("mov.b64 %0, {%1,%2};" : "=l"(d) : "f"(a), "f"(b));
    return d;
}
__device__ __forceinline__ float2 upk(u64 p) {
    float2 r;
    asm("mov.b64 {%0,%1}, %2;" : "=f"(r.x), "=f"(r.y) : "l"(p));
    return r;
}

// ---------------------------------------------------------------------------
// Forward recursion (blocks 0..63), linear domain, TWO CHAINS PER WARP:
//   s_{t+1}[j] = (sum_i s_t[i] * E[i][j]) * exp(e_t[j]),  E = exp(trans)
// One warp per SMSP (proven geometry); each warp interleaves two independent
// batch chains in its instruction stream — chain B's FFMA2s fill chain A's
// sync/LDS/tail latency (ILP, not TLP; cross-warp filling was falsified in
// R5/R9/R11). Both chains SHARE the E register tiles. Thread c owns columns
// (2c, 2c+1) of both chains. Renorm every 8 steps by 2^-ke from the exponent
// bits of s[0]. Gold scores: blocks 64..79 on idle SMs.
// ---------------------------------------------------------------------------
__global__ __launch_bounds__(32 * WPB, 1) void crf_fused(
    const float* __restrict__ em,    // [B, S, T]
    const int*   __restrict__ tags,  // [B, S]
    const float* __restrict__ mask,  // [B, S]
    const float* __restrict__ tr)    // [T, T]
{
    const int w    = threadIdx.x >> 5;
    const int lane = threadIdx.x & 31;

    if (blockIdx.x >= FWD_BLOCKS) {
        // ------- gold blocks: 4 warps/block, 8 batches per warp -------
        const int gw = (blockIdx.x - FWD_BLOCKS) * WPB + w;  // 0..63
        for (int k = 0; k < 8; k++) {
            const int b = gw * 8 + k;
            const int* tg = tags + b * Sn;
            const float* eb = em + (size_t)b * Sn * Tn;
            float acc = 0.0f;
            for (int sx = 1 + lane; sx < Sn; sx += 32) {
                int   t1  = __ldg(tg + sx);
                int   t0  = __ldg(tg + sx - 1);
                float mt  = __ldg(mask + b * Sn + sx);
                float emv = __ldg(eb + (size_t)sx * Tn + t1);
                float trv = __ldg(tr + t0 * Tn + t1);
                acc += (emv + trv) * mt;
            }
#pragma unroll
            for (int o = 16; o; o >>= 1)
                acc += __shfl_xor_sync(0xffffffffu, acc, o);
            if (lane == 0) g_sc[b] = acc;
        }
        return;
    }

    // ---------------- forward: warp w owns batches bA, bB ----------------
    const int c  = lane;                          // column pair (2c, 2c+1)
    const int gb = blockIdx.x * WPB + w;          // global warp id 0..255
    const int bA = 2 * gb;
    const int bB = 2 * gb + 1;

    __shared__ __align__(16) u64 sbuf[WPB][2][2][32]; // [warp][chain][buf][c]
    __shared__ float mA_[WPB][Sn];                    // mask rows (plain f32)
    __shared__ float mB_[WPB][Sn];

    for (int i = c; i < Sn; i += 32) {
        mA_[w][i] = mask[bA * Sn + i];
        mB_[w][i] = mask[bB * Sn + i];
    }

    // Shared E register tiles: EA[p] = (E[2p][2c], E[2p+1][2c]), EB col 2c+1
    u64 EA[32], EB[32];
#pragma unroll
    for (int p = 0; p < 32; p++) {
        EA[p] = pk2(__expf(tr[(2 * p) * Tn + 2 * c]),
                    __expf(tr[(2 * p + 1) * Tn + 2 * c]));
        EB[p] = pk2(__expf(tr[(2 * p) * Tn + 2 * c + 1]),
                    __expf(tr[(2 * p + 1) * Tn + 2 * c + 1]));
    }

    // Emission streams: raw float2 loaded 8 steps ahead (per chain)
    const float2* epA = (const float2*)(em + (size_t)bA * Sn * Tn) + c;
    const float2* epB = (const float2*)(em + (size_t)bB * Sn * Tn) + c;
    float2 erA[8], erB[8];
#pragma unroll
    for (int d = 0; d < 8; d++) { erA[d] = __ldg(epA + d * 32);
                                  erB[d] = __ldg(epB + d * 32); }

    u64 sA = pk2(1.0f, 1.0f), sB = pk2(1.0f, 1.0f);
    int okA = 0, okB = 0;
    __syncwarp();

    for (int tb = 0; tb < Sn; tb += 8) {
#pragma unroll
        for (int u = 0; u < 8; u++) {
            const int t   = tb + u;
            const int par = u & 1;

            // publish both chains' pairs; one sync covers both
            sbuf[w][0][par][c] = sA;
            sbuf[w][1][par][c] = sB;

            // independent work rides the sync window
            float mA = mA_[w][t], mB = mB_[w][t];
            float2 eA = erA[u],  eB = erB[u];
            u64 fA = pk2(__expf(eA.x), __expf(eA.y));
            u64 fB = pk2(__expf(eB.x), __expf(eB.y));
            if (t + 8 < Sn) { erA[u] = __ldg(epA + (size_t)(t + 8) * 32);
                              erB[u] = __ldg(epB + (size_t)(t + 8) * 32); }

            __syncwarp();

            // interleaved matvecs: 32 LDS.128, 128 FFMA2 (8 acc chains each)
            const u64* svA = &sbuf[w][0][par][0];
            const u64* svB = &sbuf[w][1][par][0];
            u64 aA0 = 0, aA1 = 0, aA2 = 0, aA3 = 0;
            u64 bA0 = 0, bA1 = 0, bA2 = 0, bA3 = 0;
            u64 aB0 = 0, aB1 = 0, aB2 = 0, aB3 = 0;
            u64 bB0 = 0, bB1 = 0, bB2 = 0, bB3 = 0;
            u64 v0A, v0B;
#pragma unroll
            for (int p = 0; p < 32; p += 4) {
                ulonglong2 xA = *(const ulonglong2*)&svA[p];
                ulonglong2 yA = *(const ulonglong2*)&svA[p + 2];
                ulonglong2 xB = *(const ulonglong2*)&svB[p];
                ulonglong2 yB = *(const ulonglong2*)&svB[p + 2];
                if (p == 0) { v0A = xA.x; v0B = xB.x; }
                aA0 = ffma2(xA.x, EA[p + 0], aA0);
                bA0 = ffma2(xA.x, EB[p + 0], bA0);
                aB0 = ffma2(xB.x, EA[p + 0], aB0);
                bB0 = ffma2(xB.x, EB[p + 0], bB0);
                aA1 = ffma2(xA.y, EA[p + 1], aA1);
                bA1 = ffma2(xA.y, EB[p + 1], bA1);
                aB1 = ffma2(xB.y, EA[p + 1], aB1);
                bB1 = ffma2(xB.y, EB[p + 1], bB1);
                aA2 = ffma2(yA.x, EA[p + 2], aA2);
                bA2 = ffma2(yA.x, EB[p + 2], bA2);
                aB2 = ffma2(yB.x, EA[p + 2], aB2);
                bB2 = ffma2(yB.x, EB[p + 2], bB2);
                aA3 = ffma2(yA.y, EA[p + 3], aA3);
                bA3 = ffma2(yA.y, EB[p + 3], bA3);
                aB3 = ffma2(yB.y, EA[p + 3], aB3);
                bB3 = ffma2(yB.y, EB[p + 3], bB3);
            }
            // chain A tail
            {
                u64 sa = fadd2(fadd2(aA0, aA1), fadd2(aA2, aA3));
                u64 sb = fadd2(fadd2(bA0, bA1), fadd2(bA2, bA3));
                float2 fa = upk(sa), fb = upk(sb);
                u64 qf = fmul2(pk2(fa.x + fa.y, fb.x + fb.y), fA);
                float om = 1.0f - mA;
                u64 sn = ffma2(pk2(om, om), sA, fmul2(pk2(mA, mA), qf));
                if (u == 7) {
                    int ke = ((__float_as_int(upk(v0A).x) >> 23) & 0xff) - 127;
                    okA += ke;
                    float sc = __int_as_float((127 - ke) << 23);
                    sn = fmul2(sn, pk2(sc, sc));
                }
                sA = sn;
            }
            // chain B tail
            {
                u64 sa = fadd2(fadd2(aB0, aB1), fadd2(aB2, aB3));
                u64 sb = fadd2(fadd2(bB0, bB1), fadd2(bB2, bB3));
                float2 fa = upk(sa), fb = upk(sb);
                u64 qf = fmul2(pk2(fa.x + fa.y, fb.x + fb.y), fB);
                float om = 1.0f - mB;
                u64 sn = ffma2(pk2(om, om), sB, fmul2(pk2(mB, mB), qf));
                if (u == 7) {
                    int ke = ((__float_as_int(upk(v0B).x) >> 23) & 0xff) - 127;
                    okB += ke;
                    float sc = __int_as_float((127 - ke) << 23);
                    sn = fmul2(sn, pk2(sc, sc));
                }
                sB = sn;
            }
        }
    }

    // z[b] = offk*ln2 + log(sum_j s[j]) for both chains
    float2 pA = upk(sA), pB = upk(sB);
    float xA = pA.x + pA.y, xB = pB.x + pB.y;
#pragma unroll
    for (int o = 16; o; o >>= 1) {
        xA += __shfl_xor_sync(0xffffffffu, xA, o);
        xB += __shfl_xor_sync(0xffffffffu, xB, o);
    }
    if (lane == 0) {
        g_z[bA] = (float)((double)okA * 0.6931471805599453 + (double)logf(xA));
        g_z[bB] = (float)((double)okB * 0.6931471805599453 + (double)logf(xB));
    }
}

// ---------------------------------------------------------------------------
// out = -mean(z - score)
// ---------------------------------------------------------------------------
__global__ __launch_bounds__(Bn) void crf_final(float* __restrict__ out)
{
    __shared__ float red[Bn];
    const int tid = threadIdx.x;
    red[tid] = g_z[tid] - g_sc[tid];
    __syncthreads();
    for (int st = Bn / 2; st; st >>= 1) {
        if (tid < st) red[tid] += red[tid + st];
        __syncthreads();
    }
    if (tid == 0) out[0] = -red[0] / (float)Bn;
}

extern "C" void kernel_launch(void* const* d_in, const int* in_sizes, int n_in,
                              void* d_out, int out_size)
{
    const float* em   = (const float*)d_in[0];  // emissions [B,S,T] f32
    const int*   tags = (const int*)  d_in[1];  // tags [B,S] i32
    const float* mask = (const float*)d_in[2];  // mask [B,S] f32
    const float* tr   = (const float*)d_in[3];  // transitions [T,T] f32

    crf_fused<<<FWD_BLOCKS + GOLD_BLOCKS, 32 * WPB>>>(em, tags, mask, tr);
    crf_final<<<1, Bn>>>((float*)d_out);
}